// round 1
// baseline (speedup 1.0000x reference)
#include <cuda_runtime.h>
#include <math.h>

#define NN 20000
#define NE 320000
#define GAT_ALPHA 0.2f
#define GAT_EPS 1e-16f

// ---------------- scratch (device globals; no allocation allowed) ----------
__device__ float g_Wh [4u * 20000u * 256u];   // also holds 6*20000*121
__device__ float g_agg[4u * 20000u * 256u];
__device__ float g_x1 [20000u * 1024u];
__device__ float g_x2 [20000u * 1024u];
__device__ float g_ssrc[6 * 20000];
__device__ float g_sdst[6 * 20000];
__device__ float g_emax[6 * 20000];
__device__ float g_esum[6 * 20000];
__device__ float g_eexp[6 * 320000];
__device__ int   g_src[320000];
__device__ int   g_dst[320000];
__device__ int   g_is64;

// ---------------- helpers ---------------------------------------------------
__device__ __forceinline__ void atomicMaxF(float* addr, float val) {
    if (val >= 0.0f) atomicMax((int*)addr, __float_as_int(val));
    else             atomicMin((unsigned int*)addr, __float_as_uint(val));
}
__device__ __forceinline__ float eluf(float v) {
    return v > 0.0f ? v : expm1f(v);
}

// ---------------- index width detection / conversion ------------------------
__global__ void detect64_k(const void* p) {
    const unsigned int* w = (const unsigned int*)p;
    int is64 = 1;
    for (int i = 1; i < 256; i += 2)
        if (w[i] != 0u) { is64 = 0; break; }
    g_is64 = is64;
}
__global__ void convert_idx_k(const void* p, int E) {
    int i = blockIdx.x * blockDim.x + threadIdx.x;
    if (i >= E) return;
    int s, d;
    if (g_is64) {
        const long long* q = (const long long*)p;
        s = (int)q[i]; d = (int)q[E + i];
    } else {
        const int* q = (const int*)p;
        s = q[i]; d = q[E + i];
    }
    g_src[i] = s; g_dst[i] = d;
}

// ---------------- GEMM: C[h] = A (MxK) @ B[h] (KxN) -------------------------
// 64x64 tile, 256 threads, 4x4 per thread.
__global__ void gemm64_k(const float* __restrict__ A, const float* __restrict__ Bbase,
                         float* __restrict__ Cbase, int M, int N, int K) {
    int h = blockIdx.z;
    const float* B = Bbase + (size_t)h * K * N;
    float*       C = Cbase + (size_t)h * M * N;
    __shared__ float As[16][64];
    __shared__ float Bs[16][64];
    int tid = threadIdx.x;
    int tx = tid & 15, ty = tid >> 4;
    int row0 = blockIdx.y * 64;
    int col0 = blockIdx.x * 64;
    float acc[4][4] = {};
    for (int k0 = 0; k0 < K; k0 += 16) {
#pragma unroll
        for (int i = 0; i < 4; i++) {
            int idx = tid + i * 256;
            int k = idx & 15, m = idx >> 4;
            int gm = row0 + m, gk = k0 + k;
            As[k][m] = (gm < M && gk < K) ? A[(size_t)gm * K + gk] : 0.0f;
        }
#pragma unroll
        for (int i = 0; i < 4; i++) {
            int idx = tid + i * 256;
            int n = idx & 63, k = idx >> 6;
            int gn = col0 + n, gk = k0 + k;
            Bs[k][n] = (gn < N && gk < K) ? B[(size_t)gk * N + gn] : 0.0f;
        }
        __syncthreads();
#pragma unroll
        for (int k = 0; k < 16; k++) {
            float ra[4], rb[4];
#pragma unroll
            for (int i = 0; i < 4; i++) ra[i] = As[k][ty * 4 + i];
#pragma unroll
            for (int j = 0; j < 4; j++) rb[j] = Bs[k][tx * 4 + j];
#pragma unroll
            for (int i = 0; i < 4; i++)
#pragma unroll
                for (int j = 0; j < 4; j++) acc[i][j] += ra[i] * rb[j];
        }
        __syncthreads();
    }
#pragma unroll
    for (int i = 0; i < 4; i++) {
        int gm = row0 + ty * 4 + i;
        if (gm >= M) continue;
#pragma unroll
        for (int j = 0; j < 4; j++) {
            int gn = col0 + tx * 4 + j;
            if (gn < N) C[(size_t)gm * N + gn] = acc[i][j];
        }
    }
}

// ---------------- per-node attention scores ---------------------------------
// s_src[h][n] = Wh[h][n] . a[h][0:F];  s_dst[h][n] = Wh[h][n] . a[h][F:2F]
__global__ void score_k(const float* __restrict__ Wh, const float* __restrict__ a,
                        float* __restrict__ ssrc, float* __restrict__ sdst,
                        int N, int F) {
    int warpsPerBlock = blockDim.x >> 5;
    int node = blockIdx.x * warpsPerBlock + (threadIdx.x >> 5);
    if (node >= N) return;
    int h = blockIdx.y;
    int lane = threadIdx.x & 31;
    const float* row = Wh + ((size_t)h * N + node) * F;
    const float* av  = a + (size_t)h * 2 * F;
    float s1 = 0.0f, s2 = 0.0f;
    for (int f = lane; f < F; f += 32) {
        float w = row[f];
        s1 += w * av[f];
        s2 += w * av[F + f];
    }
#pragma unroll
    for (int off = 16; off; off >>= 1) {
        s1 += __shfl_xor_sync(0xffffffffu, s1, off);
        s2 += __shfl_xor_sync(0xffffffffu, s2, off);
    }
    if (lane == 0) {
        ssrc[h * N + node] = s1;
        sdst[h * N + node] = s2;
    }
}

// ---------------- init ------------------------------------------------------
__global__ void zero_f_k(float* p, size_t n) {
    for (size_t i = blockIdx.x * (size_t)blockDim.x + threadIdx.x; i < n;
         i += (size_t)gridDim.x * blockDim.x)
        p[i] = 0.0f;
}
__global__ void init_ms_k(float* emax, float* esum, int n) {
    int i = blockIdx.x * blockDim.x + threadIdx.x;
    if (i < n) { emax[i] = -INFINITY; esum[i] = 0.0f; }
}

// ---------------- edge passes -----------------------------------------------
__global__ void edge_max_k(const float* __restrict__ ssrc, const float* __restrict__ sdst,
                           float* __restrict__ emax, int E, int N) {
    int idx = blockIdx.x * blockDim.x + threadIdx.x;
    int tot = E * gridDim.y;  // unused; guard below
    (void)tot;
    if (idx >= E) return;
    int h = blockIdx.y;
    int s = g_src[idx], d = g_dst[idx];
    float v = ssrc[h * N + s] + sdst[h * N + d];
    v = v > 0.0f ? v : GAT_ALPHA * v;
    atomicMaxF(&emax[h * N + d], v);
}
__global__ void edge_exp_k(const float* __restrict__ ssrc, const float* __restrict__ sdst,
                           const float* __restrict__ emax, float* __restrict__ esum,
                           float* __restrict__ eexp, int E, int N) {
    int idx = blockIdx.x * blockDim.x + threadIdx.x;
    if (idx >= E) return;
    int h = blockIdx.y;
    int s = g_src[idx], d = g_dst[idx];
    float v = ssrc[h * N + s] + sdst[h * N + d];
    v = v > 0.0f ? v : GAT_ALPHA * v;
    float ex = expf(v - emax[h * N + d]);
    eexp[(size_t)h * E + idx] = ex;
    atomicAdd(&esum[h * N + d], ex);
}
// agg[h][dst] += Wh[h][src] * att
__global__ void aggregate_k(const float* __restrict__ Wh, const float* __restrict__ eexp,
                            const float* __restrict__ esum, float* __restrict__ agg,
                            int E, int N, int F) {
    int e = blockIdx.x;
    int h = blockIdx.y;
    int s = g_src[e], d = g_dst[e];
    float att = eexp[(size_t)h * E + e] / (esum[h * N + d] + GAT_EPS);
    const float* w = Wh + ((size_t)h * N + s) * F;
    float*       o = agg + ((size_t)h * N + d) * F;
    for (int f = threadIdx.x; f < F; f += blockDim.x)
        atomicAdd(&o[f], w[f] * att);
}

// ---------------- finalize --------------------------------------------------
// out[n, h*F+f] = elu( elu(agg[h][n][f]) + (skip ? skip[n,h*F+f] : 0) )
__global__ void finalize_concat_k(const float* __restrict__ agg, const float* __restrict__ skip,
                                  float* __restrict__ out, int N, int F, int H) {
    size_t total = (size_t)N * H * F;
    for (size_t idx = blockIdx.x * (size_t)blockDim.x + threadIdx.x; idx < total;
         idx += (size_t)gridDim.x * blockDim.x) {
        int f = (int)(idx % F);
        size_t t = idx / F;
        int h = (int)(t % H);
        int n = (int)(t / H);
        float v = agg[((size_t)h * N + n) * F + f];
        v = eluf(v);
        if (skip) v += skip[idx];
        out[idx] = eluf(v);
    }
}
// out[n,f] = sigmoid( mean_h agg[h][n][f] )
__global__ void finalize_mean_k(const float* __restrict__ agg, float* __restrict__ out,
                                int N, int F, int H) {
    size_t total = (size_t)N * F;
    for (size_t idx = blockIdx.x * (size_t)blockDim.x + threadIdx.x; idx < total;
         idx += (size_t)gridDim.x * blockDim.x) {
        int f = (int)(idx % F);
        int n = (int)(idx / F);
        float sum = 0.0f;
        for (int h = 0; h < H; h++)
            sum += agg[((size_t)h * N + n) * F + f];
        float v = sum / (float)H;
        out[idx] = 1.0f / (1.0f + expf(-v));
    }
}

// ---------------- host-side layer driver ------------------------------------
struct Scratch {
    float *Wh, *agg, *x1, *x2, *ssrc, *sdst, *emax, *esum, *eexp;
};

static void run_layer(const float* in, int Fin, int Fout, int H,
                      const float* W, const float* a,
                      const float* skip, float* out, int mode,  // 1=concat,2=concat+skip,3=mean
                      int N, int E, const Scratch& sc) {
    // 1. GEMM per head
    dim3 gg((Fout + 63) / 64, (N + 63) / 64, H);
    gemm64_k<<<gg, 256>>>(in, W, sc.Wh, N, Fout, Fin);
    // 2. scores
    dim3 gs((N + 3) / 4, H);
    score_k<<<gs, 128>>>(sc.Wh, a, sc.ssrc, sc.sdst, N, Fout);
    // 3. init
    size_t aggN = (size_t)H * N * Fout;
    zero_f_k<<<2048, 256>>>(sc.agg, aggN);
    init_ms_k<<<(H * N + 255) / 256, 256>>>(sc.emax, sc.esum, H * N);
    // 4. segment max
    dim3 ge((E + 255) / 256, H);
    edge_max_k<<<ge, 256>>>(sc.ssrc, sc.sdst, sc.emax, E, N);
    // 5. exp + segment sum
    edge_exp_k<<<ge, 256>>>(sc.ssrc, sc.sdst, sc.emax, sc.esum, sc.eexp, E, N);
    // 6. weighted scatter
    dim3 ga(E, H);
    aggregate_k<<<ga, 128>>>(sc.Wh, sc.eexp, sc.esum, sc.agg, E, N, Fout);
    // 7. finalize
    if (mode == 3) {
        finalize_mean_k<<<2048, 256>>>(sc.agg, out, N, Fout, H);
    } else {
        finalize_concat_k<<<4096, 256>>>(sc.agg, (mode == 2) ? skip : nullptr, out, N, Fout, H);
    }
}

extern "C" void kernel_launch(void* const* d_in, const int* in_sizes, int n_in,
                              void* d_out, int out_size) {
    const float* x    = (const float*)d_in[0];
    const void*  eidx = d_in[1];
    const float* W1   = (const float*)d_in[2];
    const float* a1   = (const float*)d_in[3];
    const float* W2   = (const float*)d_in[4];
    const float* a2   = (const float*)d_in[5];
    const float* W3   = (const float*)d_in[6];
    const float* a3   = (const float*)d_in[7];
    float* out = (float*)d_out;

    int N = NN;
    int E = in_sizes[1] / 2;
    if (E <= 0 || E > NE) E = NE;

    Scratch sc;
    cudaGetSymbolAddress((void**)&sc.Wh,   g_Wh);
    cudaGetSymbolAddress((void**)&sc.agg,  g_agg);
    cudaGetSymbolAddress((void**)&sc.x1,   g_x1);
    cudaGetSymbolAddress((void**)&sc.x2,   g_x2);
    cudaGetSymbolAddress((void**)&sc.ssrc, g_ssrc);
    cudaGetSymbolAddress((void**)&sc.sdst, g_sdst);
    cudaGetSymbolAddress((void**)&sc.emax, g_emax);
    cudaGetSymbolAddress((void**)&sc.esum, g_esum);
    cudaGetSymbolAddress((void**)&sc.eexp, g_eexp);

    // index width detection + conversion (int64 vs int32)
    detect64_k<<<1, 1>>>(eidx);
    convert_idx_k<<<(E + 255) / 256, 256>>>(eidx, E);

    // layer 1: Fin=50, Fout=256, H=4, concat (double elu) -> x1
    run_layer(x, 50, 256, 4, W1, a1, nullptr, sc.x1, 1, N, E, sc);
    // layer 2: Fin=1024, Fout=256, H=4, concat + skip(x1) -> x2
    run_layer(sc.x1, 1024, 256, 4, W2, a2, sc.x1, sc.x2, 2, N, E, sc);
    // layer 3: Fin=1024, Fout=121, H=6, mean + sigmoid -> out
    run_layer(sc.x2, 1024, 121, 6, W3, a3, nullptr, out, 3, N, E, sc);
}

// round 2
// speedup vs baseline: 1.7132x; 1.7132x over previous
#include <cuda_runtime.h>
#include <math.h>

#define NN 20000
#define NEMAX 320000
#define GAT_ALPHA 0.2f
#define GAT_EPS 1e-16f

// ---------------- scratch (device globals) ----------------------------------
__device__ float g_Wh [4u * 20000u * 256u];   // per-head GEMM out (h-major)
__device__ float g_x1 [20000u * 1024u];
__device__ float g_x2 [20000u * 1024u];
__device__ float g_ssrc[6 * 20000];
__device__ float g_sdst[6 * 20000];
__device__ int   g_src [NEMAX];
__device__ int   g_dst [NEMAX];
__device__ int   g_cnt [NN];
__device__ int   g_ptr [NN + 1];
__device__ int   g_ofs [NN];
__device__ int   g_csrc[NEMAX];   // src node of incoming edges, grouped by dst
__device__ int   g_is64;

__device__ __forceinline__ float eluf(float v) { return v > 0.0f ? v : expm1f(v); }

// ---------------- edge index prep + CSR build -------------------------------
__global__ void detect64_k(const void* p) {
    const unsigned int* w = (const unsigned int*)p;
    int is64 = 1;
    for (int i = 1; i < 256; i += 2)
        if (w[i] != 0u) { is64 = 0; break; }
    g_is64 = is64;
}
__global__ void zero_cnt_k(int n) {
    int i = blockIdx.x * blockDim.x + threadIdx.x;
    if (i < n) g_cnt[i] = 0;
}
__global__ void convert_hist_k(const void* p, int E) {
    int i = blockIdx.x * blockDim.x + threadIdx.x;
    if (i >= E) return;
    int s, d;
    if (g_is64) {
        const long long* q = (const long long*)p;
        s = (int)q[i]; d = (int)q[E + i];
    } else {
        const int* q = (const int*)p;
        s = q[i]; d = q[E + i];
    }
    g_src[i] = s; g_dst[i] = d;
    atomicAdd(&g_cnt[d], 1);
}
__global__ void scan_k(int n) {   // single block, 256 threads
    __shared__ int sums[256];
    int tid = threadIdx.x;
    int chunk = (n + 255) / 256;
    int st = tid * chunk;
    int en = st + chunk; if (en > n) en = n;
    int s = 0;
    for (int i = st; i < en; i++) s += g_cnt[i];
    sums[tid] = s;
    __syncthreads();
    for (int off = 1; off < 256; off <<= 1) {
        int v = (tid >= off) ? sums[tid - off] : 0;
        __syncthreads();
        sums[tid] += v;
        __syncthreads();
    }
    int run = (tid > 0) ? sums[tid - 1] : 0;
    for (int i = st; i < en; i++) { g_ptr[i] = run; g_ofs[i] = run; run += g_cnt[i]; }
    if (tid == 0) g_ptr[n] = sums[255];
}
__global__ void scatter_k(int E) {
    int i = blockIdx.x * blockDim.x + threadIdx.x;
    if (i >= E) return;
    int d = g_dst[i];
    int pos = atomicAdd(&g_ofs[d], 1);
    g_csrc[pos] = g_src[i];
}

// ---------------- SGEMM: C = A(MxK) @ [W_0|W_1|..|W_{H-1}]  -----------------
// BM=128, BN=128, BK=8, 256 threads, 8x8 per thread, double-buffered smem.
// W: (H, K, Fh); output written h-major: C[((h*M + m)*Fh) + f].
__global__ void __launch_bounds__(256)
sgemm_k(const float* __restrict__ A, const float* __restrict__ W,
        float* __restrict__ C, int M, int K, int Fh, int H) {
    __shared__ float As[2][8][128];
    __shared__ float Bs[2][8][128];
    int tid = threadIdx.x;
    int tx = tid & 15, ty = tid >> 4;
    int row0 = blockIdx.y * 128, col0 = blockIdx.x * 128;
    int Ntot = Fh * H;

    // A loader: 4 scalars per thread (row ar, cols ak0..ak0+3)
    int ar = tid >> 1, ak0 = (tid & 1) * 4;
    const float* Ap = A + (size_t)(row0 + ar) * K;
    bool a_ok = (row0 + ar) < M;
    // B loader: 4 scalars per thread (k row bk, cols bc0..bc0+3); precompute head ptrs
    int bk = tid >> 5, bc0 = (tid & 31) * 4;
    const float* Wp[4]; bool b_ok[4];
    #pragma unroll
    for (int i = 0; i < 4; i++) {
        int gc = col0 + bc0 + i;
        b_ok[i] = gc < Ntot;
        int h = b_ok[i] ? gc / Fh : 0;
        int f = b_ok[i] ? gc - h * Fh : 0;
        Wp[i] = W + (size_t)h * K * Fh + f;
    }

    float acc[8][8] = {};
    float la[4], lb[4];

    // prologue: tile 0 -> buf 0
    #pragma unroll
    for (int i = 0; i < 4; i++) {
        int gk = ak0 + i;
        As[0][ak0 + i][ar] = (a_ok && gk < K) ? Ap[gk] : 0.0f;
    }
    #pragma unroll
    for (int i = 0; i < 4; i++) {
        Bs[0][bk][bc0 + i] = (b_ok[i] && bk < K) ? Wp[i][(size_t)bk * Fh] : 0.0f;
    }
    __syncthreads();

    int nk = (K + 7) / 8;
    for (int t = 0; t < nk; t++) {
        int buf = t & 1;
        if (t + 1 < nk) {
            int k0 = (t + 1) * 8;
            #pragma unroll
            for (int i = 0; i < 4; i++) {
                int gk = k0 + ak0 + i;
                la[i] = (a_ok && gk < K) ? Ap[gk] : 0.0f;
            }
            int gk = k0 + bk;
            #pragma unroll
            for (int i = 0; i < 4; i++)
                lb[i] = (b_ok[i] && gk < K) ? Wp[i][(size_t)gk * Fh] : 0.0f;
        }
        #pragma unroll
        for (int kk = 0; kk < 8; kk++) {
            float4 a0 = *(const float4*)&As[buf][kk][ty * 8];
            float4 a1 = *(const float4*)&As[buf][kk][ty * 8 + 4];
            float4 b0 = *(const float4*)&Bs[buf][kk][tx * 8];
            float4 b1 = *(const float4*)&Bs[buf][kk][tx * 8 + 4];
            float av[8] = {a0.x, a0.y, a0.z, a0.w, a1.x, a1.y, a1.z, a1.w};
            float bv[8] = {b0.x, b0.y, b0.z, b0.w, b1.x, b1.y, b1.z, b1.w};
            #pragma unroll
            for (int i = 0; i < 8; i++)
                #pragma unroll
                for (int j = 0; j < 8; j++)
                    acc[i][j] += av[i] * bv[j];
        }
        if (t + 1 < nk) {
            #pragma unroll
            for (int i = 0; i < 4; i++) As[1 - buf][ak0 + i][ar] = la[i];
            #pragma unroll
            for (int i = 0; i < 4; i++) Bs[1 - buf][bk][bc0 + i] = lb[i];
        }
        __syncthreads();
    }

    #pragma unroll
    for (int i = 0; i < 8; i++) {
        int gm = row0 + ty * 8 + i;
        if (gm >= M) continue;
        #pragma unroll
        for (int j = 0; j < 8; j++) {
            int gc = col0 + tx * 8 + j;
            if (gc >= Ntot) continue;
            int h = gc / Fh, f = gc - h * Fh;
            C[((size_t)h * M + gm) * Fh + f] = acc[i][j];
        }
    }
}

// ---------------- per-node attention scores ---------------------------------
__global__ void score_k(const float* __restrict__ Wh, const float* __restrict__ a,
                        float* __restrict__ ssrc, float* __restrict__ sdst,
                        int N, int F) {
    int node = blockIdx.x * (blockDim.x >> 5) + (threadIdx.x >> 5);
    if (node >= N) return;
    int h = blockIdx.y;
    int lane = threadIdx.x & 31;
    const float* row = Wh + ((size_t)h * N + node) * F;
    const float* av  = a + (size_t)h * 2 * F;
    float s1 = 0.0f, s2 = 0.0f;
    for (int f = lane; f < F; f += 32) {
        float w = row[f];
        s1 += w * av[f];
        s2 += w * av[F + f];
    }
    #pragma unroll
    for (int off = 16; off; off >>= 1) {
        s1 += __shfl_xor_sync(0xffffffffu, s1, off);
        s2 += __shfl_xor_sync(0xffffffffu, s2, off);
    }
    if (lane == 0) {
        ssrc[h * N + node] = s1;
        sdst[h * N + node] = s2;
    }
}

// ---------------- fused attention + aggregation (concat layers) -------------
// warp per (dst, head); F = 32*NJ. out[d*H*F + h*F + f] = elu(elu(acc)+skip)
template <int NJ>
__global__ void __launch_bounds__(256)
agg_concat_k(const float* __restrict__ Wh, const float* __restrict__ ssrc,
             const float* __restrict__ sdst, const float* __restrict__ skip,
             float* __restrict__ out, int N, int F, int H) {
    int wid = (blockIdx.x * blockDim.x + threadIdx.x) >> 5;
    int lane = threadIdx.x & 31;
    if (wid >= N * H) return;
    int d = wid / H, h = wid - d * H;
    int beg = g_ptr[d], end = g_ptr[d + 1];
    float sd = sdst[h * N + d];
    const float* ss = ssrc + (size_t)h * N;

    float m = -INFINITY;
    for (int i = beg + lane; i < end; i += 32) {
        float v = ss[g_csrc[i]] + sd;
        v = v > 0.0f ? v : GAT_ALPHA * v;
        m = fmaxf(m, v);
    }
    #pragma unroll
    for (int off = 16; off; off >>= 1) m = fmaxf(m, __shfl_xor_sync(0xffffffffu, m, off));
    float ssum = 0.0f;
    for (int i = beg + lane; i < end; i += 32) {
        float v = ss[g_csrc[i]] + sd;
        v = v > 0.0f ? v : GAT_ALPHA * v;
        ssum += expf(v - m);
    }
    #pragma unroll
    for (int off = 16; off; off >>= 1) ssum += __shfl_xor_sync(0xffffffffu, ssum, off);
    float inv = 1.0f / (ssum + GAT_EPS);

    float acc[NJ];
    #pragma unroll
    for (int j = 0; j < NJ; j++) acc[j] = 0.0f;
    for (int e = beg; e < end; e++) {
        int s = g_csrc[e];
        float v = ss[s] + sd;
        v = v > 0.0f ? v : GAT_ALPHA * v;
        float att = expf(v - m) * inv;
        const float* w = Wh + ((size_t)h * N + s) * F;
        #pragma unroll
        for (int j = 0; j < NJ; j++) acc[j] += w[lane + 32 * j] * att;
    }
    size_t base = ((size_t)d * H + h) * F;
    #pragma unroll
    for (int j = 0; j < NJ; j++) {
        float v = eluf(acc[j]);
        if (skip) v += skip[base + lane + 32 * j];
        out[base + lane + 32 * j] = eluf(v);
    }
}

// ---------------- fused attention + aggregation (mean layer) ----------------
// warp per dst; loops heads internally; out[d*F+f] = sigmoid(sum_h acc_h / H)
template <int NJ>
__global__ void __launch_bounds__(256)
agg_mean_k(const float* __restrict__ Wh, const float* __restrict__ ssrc,
           const float* __restrict__ sdst, float* __restrict__ out,
           int N, int F, int H) {
    int d = (blockIdx.x * blockDim.x + threadIdx.x) >> 5;
    int lane = threadIdx.x & 31;
    if (d >= N) return;
    int beg = g_ptr[d], end = g_ptr[d + 1];
    float accs[NJ];
    #pragma unroll
    for (int j = 0; j < NJ; j++) accs[j] = 0.0f;

    for (int h = 0; h < H; h++) {
        float sd = sdst[h * N + d];
        const float* ss = ssrc + (size_t)h * N;
        float m = -INFINITY;
        for (int i = beg + lane; i < end; i += 32) {
            float v = ss[g_csrc[i]] + sd;
            v = v > 0.0f ? v : GAT_ALPHA * v;
            m = fmaxf(m, v);
        }
        #pragma unroll
        for (int off = 16; off; off >>= 1) m = fmaxf(m, __shfl_xor_sync(0xffffffffu, m, off));
        float ssum = 0.0f;
        for (int i = beg + lane; i < end; i += 32) {
            float v = ss[g_csrc[i]] + sd;
            v = v > 0.0f ? v : GAT_ALPHA * v;
            ssum += expf(v - m);
        }
        #pragma unroll
        for (int off = 16; off; off >>= 1) ssum += __shfl_xor_sync(0xffffffffu, ssum, off);
        float inv = 1.0f / (ssum + GAT_EPS);
        for (int e = beg; e < end; e++) {
            int s = g_csrc[e];
            float v = ss[s] + sd;
            v = v > 0.0f ? v : GAT_ALPHA * v;
            float att = expf(v - m) * inv;
            const float* w = Wh + ((size_t)h * N + s) * F;
            #pragma unroll
            for (int j = 0; j < NJ; j++) {
                int f = lane + 32 * j;
                if (f < F) accs[j] += w[f] * att;
            }
        }
    }
    float invH = 1.0f / (float)H;
    #pragma unroll
    for (int j = 0; j < NJ; j++) {
        int f = lane + 32 * j;
        if (f < F) out[(size_t)d * F + f] = 1.0f / (1.0f + expf(-accs[j] * invH));
    }
}

// ---------------- host driver -----------------------------------------------
extern "C" void kernel_launch(void* const* d_in, const int* in_sizes, int n_in,
                              void* d_out, int out_size) {
    const float* x    = (const float*)d_in[0];
    const void*  eidx = d_in[1];
    const float* W1   = (const float*)d_in[2];
    const float* a1   = (const float*)d_in[3];
    const float* W2   = (const float*)d_in[4];
    const float* a2   = (const float*)d_in[5];
    const float* W3   = (const float*)d_in[6];
    const float* a3   = (const float*)d_in[7];
    float* out = (float*)d_out;

    int N = NN;
    int E = in_sizes[1] / 2;
    if (E <= 0 || E > NEMAX) E = NEMAX;

    float *Wh, *x1, *x2, *ssrc, *sdst;
    cudaGetSymbolAddress((void**)&Wh,   g_Wh);
    cudaGetSymbolAddress((void**)&x1,   g_x1);
    cudaGetSymbolAddress((void**)&x2,   g_x2);
    cudaGetSymbolAddress((void**)&ssrc, g_ssrc);
    cudaGetSymbolAddress((void**)&sdst, g_sdst);

    // --- CSR build (once; shared by all 3 layers) ---
    detect64_k<<<1, 1>>>(eidx);
    zero_cnt_k<<<(N + 255) / 256, 256>>>(N);
    convert_hist_k<<<(E + 255) / 256, 256>>>(eidx, E);
    scan_k<<<1, 256>>>(N);
    scatter_k<<<(E + 255) / 256, 256>>>(E);

    // --- layer 1: Fin=50, Fout=256, H=4, concat ---
    {
        dim3 g((1024 + 127) / 128, (N + 127) / 128);
        sgemm_k<<<g, 256>>>(x, W1, Wh, N, 50, 256, 4);
        dim3 gs((N + 3) / 4, 4);
        score_k<<<gs, 128>>>(Wh, a1, ssrc, sdst, N, 256);
        int warps = N * 4;
        agg_concat_k<8><<<(warps * 32 + 255) / 256, 256>>>(Wh, ssrc, sdst, nullptr, x1, N, 256, 4);
    }
    // --- layer 2: Fin=1024, Fout=256, H=4, concat + skip ---
    {
        dim3 g((1024 + 127) / 128, (N + 127) / 128);
        sgemm_k<<<g, 256>>>(x1, W2, Wh, N, 1024, 256, 4);
        dim3 gs((N + 3) / 4, 4);
        score_k<<<gs, 128>>>(Wh, a2, ssrc, sdst, N, 256);
        int warps = N * 4;
        agg_concat_k<8><<<(warps * 32 + 255) / 256, 256>>>(Wh, ssrc, sdst, x1, x2, N, 256, 4);
    }
    // --- layer 3: Fin=1024, Fout=121, H=6, mean + sigmoid ---
    {
        dim3 g((726 + 127) / 128, (N + 127) / 128);
        sgemm_k<<<g, 256>>>(x2, W3, Wh, N, 1024, 121, 6);
        dim3 gs((N + 3) / 4, 6);
        score_k<<<gs, 128>>>(Wh, a3, ssrc, sdst, N, 121);
        agg_mean_k<4><<<(N * 32 + 255) / 256, 256>>>(Wh, ssrc, sdst, out, N, 121, 6);
    }
}